// round 1
// baseline (speedup 1.0000x reference)
#include <cuda_runtime.h>

#define Bn 4
#define Hh 512
#define Ww 512
#define HW (Hh*Ww)
#define Ntot (Bn*HW)
#define EPSf 1e-8f
#define NITER 20
#define TILE 32
#define RGN 33      // TILE + 1 halo (right/bottom) for u_new
#define SPITCH 34   // smem row pitch (bank-friendly)

// Ping-pong state + precomputed fields (static device globals: no runtime alloc)
__device__ float g_rho[Ntot];
__device__ float g_gx[Ntot];
__device__ float g_gy[Ntot];
__device__ float g_u[2][2*Ntot];   // [buf][ch*Ntot + idx], ch in {0,1}
__device__ float g_p[2][4*Ntot];   // [buf][ch*Ntot + idx], ch: p1x,p1y,p2x,p2y

__global__ void init_kernel() {
    int i = blockIdx.x*blockDim.x + threadIdx.x;
    if (i < Ntot) {
        g_u[0][i] = 0.f; g_u[0][Ntot+i] = 0.f;
        g_p[0][i] = 0.f; g_p[0][Ntot+i] = 0.f;
        g_p[0][2*Ntot+i] = 0.f; g_p[0][3*Ntot+i] = 0.f;
    }
}

// rho_c = I1 - I0 ; grad_im = K_GRAD * I1 (cross-correlation, zero pad)
__global__ void pre_kernel(const float* __restrict__ x) {
    int i = blockIdx.x*blockDim.x + threadIdx.x;
    if (i >= Ntot) return;
    int b = i >> 18;            // HW = 2^18
    int hw = i & (HW-1);
    int h = hw >> 9;            // W = 2^9
    int w = hw & (Ww-1);
    const float* I0 = x + (size_t)b*2*HW;
    const float* I1 = I0 + HW;
    g_rho[i] = I1[hw] - I0[hw];

    auto at = [&](int dh, int dw) -> float {
        int hh = h+dh, ww = w+dw;
        if (hh < 0 || hh >= Hh || ww < 0 || ww >= Ww) return 0.f;
        return I1[hh*Ww + ww];
    };
    float a00=at(-1,-1), a01=at(-1,0), a02=at(-1,1);
    float a10=at( 0,-1),               a12=at( 0,1);
    float a20=at( 1,-1), a21=at( 1,0), a22=at( 1,1);
    g_gx[i] = (-a00 + a02 - 2.f*a10 + 2.f*a12 - a20 + a22) * (1.f/6.f);
    g_gy[i] = (-a00 - 2.f*a01 - a02 + a20 + 2.f*a21 + a22) * (1.f/6.f);
}

// One full TV-L1 iteration, fused: u-update (33x33 incl. halo, via SMEM)
// then p-update (32x32 tile). Reads buf `src`, writes buf `src^1`.
__global__ void iter_kernel(int src,
    const float* __restrict__ lam_p, const float* __restrict__ tau_p,
    const float* __restrict__ theta_p,
    const float* __restrict__ wx, const float* __restrict__ wy)
{
    const float lam = lam_p[0], tau = tau_p[0], theta = theta_p[0];
    const float tl = theta * lam;
    const float rr = tau / theta;
    const float wx0 = wx[0], wx1 = wx[1], wx2 = wx[2];
    const float wy0 = wy[0], wy1 = wy[1], wy2 = wy[2];

    const float* __restrict__ u_in  = g_u[src];
    const float* __restrict__ p_in  = g_p[src];
    float* __restrict__ u_out = g_u[src^1];
    float* __restrict__ p_out = g_p[src^1];

    const int b  = blockIdx.z;
    const int h0 = blockIdx.y * TILE;
    const int w0 = blockIdx.x * TILE;
    const int base = b * HW;

    __shared__ float s_u0[RGN*SPITCH];
    __shared__ float s_u1[RGN*SPITCH];

    const int tid = threadIdx.x;

    // ---- Phase 1: u_new on 33x33 region (zero outside image = zero-pad) ----
    for (int k = tid; k < RGN*RGN; k += blockDim.x) {
        int lr = k / RGN;
        int lc = k - lr*RGN;
        int h = h0 + lr, w = w0 + lc;
        float un0 = 0.f, un1 = 0.f;
        if (h < Hh && w < Ww) {
            int idx = base + h*Ww + w;
            float gx = g_gx[idx], gy = g_gy[idx];
            float u0 = u_in[idx], u1 = u_in[Ntot + idx];
            float rho = g_rho[idx] + gx*u0 + gy*u1;
            float ng = gx*gx + gy*gy + EPSf;
            float th = tl * ng;
            float d0, d1;
            if (fabsf(rho) < th) {
                float inv = 1.0f / ng;
                d0 = rho*gx*inv; d1 = rho*gy*inv;
            } else {
                float s = (rho > 0.f) ? 1.f : ((rho < 0.f) ? -1.f : 0.f);
                d0 = tl*gx*s; d1 = tl*gy*s;
            }
            const float* p1x = p_in;
            const float* p1y = p_in + Ntot;
            const float* p2x = p_in + 2*Ntot;
            const float* p2y = p_in + 3*Ntot;
            float div1 = wx1*p1x[idx] + wy1*p1y[idx];
            float div2 = wx1*p2x[idx] + wy1*p2y[idx];
            if (w > 0)      { div1 += wx0*p1x[idx-1];  div2 += wx0*p2x[idx-1];  }
            if (w < Ww-1)   { div1 += wx2*p1x[idx+1];  div2 += wx2*p2x[idx+1];  }
            if (h > 0)      { div1 += wy0*p1y[idx-Ww]; div2 += wy0*p2y[idx-Ww]; }
            if (h < Hh-1)   { div1 += wy2*p1y[idx+Ww]; div2 += wy2*p2y[idx+Ww]; }
            un0 = (u0 - d0) + theta*div1;
            un1 = (u1 - d1) + theta*div2;
            if (lr < TILE && lc < TILE) {           // interior: this block owns it
                u_out[idx]        = un0;
                u_out[Ntot + idx] = un1;
            }
        }
        s_u0[lr*SPITCH + lc] = un0;
        s_u1[lr*SPITCH + lc] = un1;
    }
    __syncthreads();

    // ---- Phase 2: p_new on 32x32 tile from SMEM u_new (forward diffs) ----
    for (int k = tid; k < TILE*TILE; k += blockDim.x) {
        int lr = k >> 5;
        int lc = k & 31;
        int h = h0 + lr, w = w0 + lc;
        if (h >= Hh || w >= Ww) continue;
        int idx = base + h*Ww + w;
        float c0  = s_u0[lr*SPITCH + lc];
        float gx0 = s_u0[lr*SPITCH + lc + 1]   - c0;
        float gy0 = s_u0[(lr+1)*SPITCH + lc]   - c0;
        float c1  = s_u1[lr*SPITCH + lc];
        float gx1 = s_u1[lr*SPITCH + lc + 1]   - c1;
        float gy1 = s_u1[(lr+1)*SPITCH + lc]   - c1;
        float den1 = 1.f + rr*(fabsf(gx0) + fabsf(gy0));
        float den2 = 1.f + rr*(fabsf(gx1) + fabsf(gy1));
        float i1 = 1.f/den1, i2 = 1.f/den2;
        p_out[idx]          = (p_in[idx]          + rr*gx0) * i1;
        p_out[Ntot + idx]   = (p_in[Ntot + idx]   + rr*gy0) * i1;
        p_out[2*Ntot + idx] = (p_in[2*Ntot + idx] + rr*gx1) * i2;
        p_out[3*Ntot + idx] = (p_in[3*Ntot + idx] + rr*gy1) * i2;
    }
}

// AvgPool2d(3, stride 1, pad 1, count_include_pad -> always /9)
__global__ void avg_kernel(float* __restrict__ out) {
    int o = blockIdx.x*blockDim.x + threadIdx.x;
    if (o >= 2*Ntot) return;
    int w = o & (Ww-1);
    int h = (o >> 9) & (Hh-1);
    int c = (o >> 18) & 1;
    int b = o >> 19;
    const float* u = g_u[0] + c*Ntot + b*HW;   // final state lands in buf 0 after 20 iters
    float s = 0.f;
    #pragma unroll
    for (int dh = -1; dh <= 1; dh++) {
        int hh = h + dh;
        if (hh < 0 || hh >= Hh) continue;
        #pragma unroll
        for (int dw = -1; dw <= 1; dw++) {
            int ww = w + dw;
            if (ww < 0 || ww >= Ww) continue;
            s += u[hh*Ww + ww];
        }
    }
    out[o] = s * (1.f/9.f);
}

extern "C" void kernel_launch(void* const* d_in, const int* in_sizes, int n_in,
                              void* d_out, int out_size) {
    const float* x     = (const float*)d_in[0];
    const float* lam   = (const float*)d_in[1];
    const float* tau   = (const float*)d_in[2];
    const float* theta = (const float*)d_in[3];
    const float* wx    = (const float*)d_in[4];
    const float* wy    = (const float*)d_in[5];
    float* out = (float*)d_out;

    init_kernel<<<(Ntot + 255)/256, 256>>>();
    pre_kernel<<<(Ntot + 255)/256, 256>>>(x);

    dim3 grid(Ww/TILE, Hh/TILE, Bn);   // 16 x 16 x 4 = 1024 blocks
    for (int i = 0; i < NITER; i++)
        iter_kernel<<<grid, 256>>>(i & 1, lam, tau, theta, wx, wy);

    avg_kernel<<<(2*Ntot + 255)/256, 256>>>(out);
}

// round 2
// speedup vs baseline: 1.6250x; 1.6250x over previous
#include <cuda_runtime.h>

#define Bn 4
#define Hh 512
#define Ww 512
#define HW (Hh*Ww)
#define Ntot (Bn*HW)
#define EPSf 1e-8f
#define NITER 20
#define TILE 31        // owned interior per block
#define RGN 32         // computed region (TILE + 1 halo, = warp width)
#define NT 17          // ceil(512/31)
#define SP 33          // smem pitch in float2

// State in vector-packed device globals (no runtime alloc)
__device__ float4 g_cfg[Ntot];        // (rho, gx, gy, pad)
__device__ float2 g_u2[2][Ntot];      // (u0, u1)
__device__ float4 g_p4[2][Ntot];      // (p1x, p1y, p2x, p2y)

__global__ void init_kernel() {
    int i = blockIdx.x*blockDim.x + threadIdx.x;
    if (i < Ntot) {
        g_u2[0][i] = make_float2(0.f, 0.f);
        g_p4[0][i] = make_float4(0.f, 0.f, 0.f, 0.f);
    }
}

// cfg = (I1-I0, K_GRAD_x*I1, K_GRAD_y*I1) with zero padding
__global__ void pre_kernel(const float* __restrict__ x) {
    int i = blockIdx.x*blockDim.x + threadIdx.x;
    if (i >= Ntot) return;
    int b = i >> 18;
    int hw = i & (HW-1);
    int h = hw >> 9;
    int w = hw & (Ww-1);
    const float* I0 = x + (size_t)b*2*HW;
    const float* I1 = I0 + HW;

    auto at = [&](int dh, int dw) -> float {
        int hh = h+dh, ww = w+dw;
        if (hh < 0 || hh >= Hh || ww < 0 || ww >= Ww) return 0.f;
        return I1[hh*Ww + ww];
    };
    float a00=at(-1,-1), a01=at(-1,0), a02=at(-1,1);
    float a10=at( 0,-1),               a12=at( 0,1);
    float a20=at( 1,-1), a21=at( 1,0), a22=at( 1,1);
    float gx = (-a00 + a02 - 2.f*a10 + 2.f*a12 - a20 + a22) * (1.f/6.f);
    float gy = (-a00 - 2.f*a01 - a02 + a20 + 2.f*a21 + a22) * (1.f/6.f);
    g_cfg[i] = make_float4(I1[hw] - I0[hw], gx, gy, 0.f);
}

// One fused TV-L1 iteration. 32x32 region computed (u-update), 31x31 interior
// owned (u/p written). p center kept in registers across the barrier.
__global__ __launch_bounds__(256) void iter_kernel(int src,
    const float* __restrict__ lam_p, const float* __restrict__ tau_p,
    const float* __restrict__ theta_p,
    const float* __restrict__ wx, const float* __restrict__ wy)
{
    const float theta = theta_p[0];
    const float tl = theta * lam_p[0];
    const float rr = tau_p[0] / theta;
    const float wx0 = wx[0], wx1 = wx[1], wx2 = wx[2];
    const float wy0 = wy[0], wy1 = wy[1], wy2 = wy[2];

    const float2* __restrict__ u_in = g_u2[src];
    const float4* __restrict__ p_in = g_p4[src];
    float2* __restrict__ u_out = g_u2[src^1];
    float4* __restrict__ p_out = g_p4[src^1];

    const int tx = threadIdx.x & 31;
    const int ty = threadIdx.x >> 5;
    const int b  = blockIdx.z;
    const int h0 = blockIdx.y * TILE;
    const int w0 = blockIdx.x * TILE;
    const int w  = w0 + tx;
    const int base = b * HW;

    __shared__ float2 s_u[RGN*SP];

    float4 pc[4];

    // ---- Phase 1: u_new over the full 32x32 region (zero outside image) ----
    #pragma unroll
    for (int i = 0; i < 4; i++) {
        int lr = ty + i*8;
        int h = h0 + lr;
        float2 res = make_float2(0.f, 0.f);
        float4 p = make_float4(0.f, 0.f, 0.f, 0.f);
        if (h < Hh && w < Ww) {
            int idx = base + h*Ww + w;
            float4 cfg = g_cfg[idx];
            float2 u = u_in[idx];
            p = p_in[idx];
            float4 z4 = make_float4(0.f, 0.f, 0.f, 0.f);
            float4 pl = (w > 0)    ? p_in[idx-1]  : z4;
            float4 pr = (w < Ww-1) ? p_in[idx+1]  : z4;
            float4 pu = (h > 0)    ? p_in[idx-Ww] : z4;
            float4 pd = (h < Hh-1) ? p_in[idx+Ww] : z4;
            float gx = cfg.y, gy = cfg.z;
            float rho = cfg.x + gx*u.x + gy*u.y;
            float ng = gx*gx + gy*gy + EPSf;
            float th = tl * ng;
            float d0, d1;
            if (fabsf(rho) < th) {
                float inv = 1.0f / ng;
                d0 = rho*gx*inv; d1 = rho*gy*inv;
            } else {
                float s = (rho > 0.f) ? 1.f : ((rho < 0.f) ? -1.f : 0.f);
                d0 = tl*gx*s; d1 = tl*gy*s;
            }
            float div1 = wx0*pl.x + wx1*p.x + wx2*pr.x + wy0*pu.y + wy1*p.y + wy2*pd.y;
            float div2 = wx0*pl.z + wx1*p.z + wx2*pr.z + wy0*pu.w + wy1*p.w + wy2*pd.w;
            res.x = (u.x - d0) + theta*div1;
            res.y = (u.y - d1) + theta*div2;
        }
        pc[i] = p;
        s_u[lr*SP + tx] = res;
    }
    __syncthreads();

    // ---- Phase 2: p_new + writes on the 31x31 interior, from SMEM u_new ----
    if (tx < TILE && w < Ww) {
        #pragma unroll
        for (int i = 0; i < 4; i++) {
            int lr = ty + i*8;
            if (lr >= TILE) continue;
            int h = h0 + lr;
            if (h >= Hh) continue;
            int idx = base + h*Ww + w;
            float2 c   = s_u[lr*SP + tx];
            float2 rgt = s_u[lr*SP + tx + 1];
            float2 dwn = s_u[(lr+1)*SP + tx];
            float gx0 = rgt.x - c.x, gy0 = dwn.x - c.x;
            float gx1 = rgt.y - c.y, gy1 = dwn.y - c.y;
            float i1 = 1.f / (1.f + rr*(fabsf(gx0) + fabsf(gy0)));
            float i2 = 1.f / (1.f + rr*(fabsf(gx1) + fabsf(gy1)));
            float4 p = pc[i];
            u_out[idx] = c;
            p_out[idx] = make_float4((p.x + rr*gx0)*i1,
                                     (p.y + rr*gy0)*i1,
                                     (p.z + rr*gx1)*i2,
                                     (p.w + rr*gy1)*i2);
        }
    }
}

// AvgPool2d(3, stride 1, pad 1, count_include_pad -> always /9), both channels
__global__ void avg_kernel(float* __restrict__ out) {
    int i = blockIdx.x*blockDim.x + threadIdx.x;
    if (i >= Ntot) return;
    int w = i & (Ww-1);
    int h = (i >> 9) & (Hh-1);
    int b = i >> 18;
    const float2* u = g_u2[0] + b*HW;   // final state is in buf 0 after 20 iters
    float sx = 0.f, sy = 0.f;
    #pragma unroll
    for (int dh = -1; dh <= 1; dh++) {
        int hh = h + dh;
        if (hh < 0 || hh >= Hh) continue;
        #pragma unroll
        for (int dw = -1; dw <= 1; dw++) {
            int ww = w + dw;
            if (ww < 0 || ww >= Ww) continue;
            float2 v = u[hh*Ww + ww];
            sx += v.x; sy += v.y;
        }
    }
    int o = b*2*HW + h*Ww + w;
    out[o]      = sx * (1.f/9.f);
    out[o + HW] = sy * (1.f/9.f);
}

extern "C" void kernel_launch(void* const* d_in, const int* in_sizes, int n_in,
                              void* d_out, int out_size) {
    const float* x     = (const float*)d_in[0];
    const float* lam   = (const float*)d_in[1];
    const float* tau   = (const float*)d_in[2];
    const float* theta = (const float*)d_in[3];
    const float* wx    = (const float*)d_in[4];
    const float* wy    = (const float*)d_in[5];
    float* out = (float*)d_out;

    init_kernel<<<(Ntot + 255)/256, 256>>>();
    pre_kernel<<<(Ntot + 255)/256, 256>>>(x);

    dim3 grid(NT, NT, Bn);   // 17 x 17 x 4 = 1156 blocks
    for (int i = 0; i < NITER; i++)
        iter_kernel<<<grid, 256>>>(i & 1, lam, tau, theta, wx, wy);

    avg_kernel<<<(Ntot + 255)/256, 256>>>(out);
}